// round 3
// baseline (speedup 1.0000x reference)
#include <cuda_runtime.h>
#include <math.h>

#define NN   100000
#define EE   1600000
#define FIN  128
#define FOUT 64
#define THRESH 0.48f
#define MAXN   (1.0f - 4e-3f)

// -------- scratch (device globals; no allocation allowed) --------
__device__ float g_updated [NN * FOUT];   // leaky_relu(logmap0(x) @ W_up)
__device__ float g_sumneigh[NN * FOUT];   // pass A result
__device__ float g_sel     [NN];          // hard gate per node (0/1)
__device__ float g_gate    [NN];          // weight_sel * sel
__device__ int   g_rowptr  [NN + 1];
__device__ int   g_cursor  [NN];
__device__ int   g_col     [EE];

// ---------------------------------------------------------------------------
// K1: logmap0 + GEMM (x_tan @ W_up) + leaky_relu  -> g_updated
// 16 rows per block, 256 threads. W_up (32KB) + x tile (8KB) in smem.
// logmap0 is a per-row scalar scale, applied after the raw-x GEMM.
// ---------------------------------------------------------------------------
__global__ void __launch_bounds__(256) k_up(const float* __restrict__ x,
                                            const float* __restrict__ Wup) {
    __shared__ float  xs[16][FIN];
    __shared__ float4 Ws[FIN * 16];     // W_up as [k][16 x float4] = [128][64]
    __shared__ float  sscale[16];

    int t = threadIdx.x;
    int rbase = blockIdx.x * 16;

    const float4* W4 = (const float4*)Wup;
    #pragma unroll
    for (int i = t; i < FIN * 16; i += 256) Ws[i] = W4[i];
    #pragma unroll
    for (int i = t; i < 16 * FIN; i += 256)
        xs[i >> 7][i & 127] = x[(size_t)rbase * FIN + i];
    __syncthreads();

    int w = t >> 5, lane = t & 31;
    #pragma unroll
    for (int rr = 0; rr < 2; ++rr) {
        int r = w * 2 + rr;
        float v0 = xs[r][lane], v1 = xs[r][lane + 32];
        float v2 = xs[r][lane + 64], v3 = xs[r][lane + 96];
        float s = v0 * v0 + v1 * v1 + v2 * v2 + v3 * v3;
        #pragma unroll
        for (int o = 16; o; o >>= 1) s += __shfl_xor_sync(0xffffffffu, s, o);
        if (lane == 0) {
            float n = fmaxf(sqrtf(s), 1e-15f);
            float a = fminf(fmaxf(n, -1.0f + 1e-7f), 1.0f - 1e-7f);
            float art = 0.5f * (log1pf(a) - log1pf(-a));
            sscale[r] = art / n;
        }
    }
    __syncthreads();

    int row = t >> 4;        // 0..15
    int cg  = t & 15;        // 16 col groups of 4
    float4 acc = make_float4(0.f, 0.f, 0.f, 0.f);
    #pragma unroll 8
    for (int k = 0; k < FIN; ++k) {
        float xv = xs[row][k];
        float4 wv = Ws[k * 16 + cg];
        acc.x = fmaf(xv, wv.x, acc.x);
        acc.y = fmaf(xv, wv.y, acc.y);
        acc.z = fmaf(xv, wv.z, acc.z);
        acc.w = fmaf(xv, wv.w, acc.w);
    }
    float sc = sscale[row];
    float4 o;
    float vx = acc.x * sc; o.x = vx > 0.f ? vx : 0.01f * vx;
    float vy = acc.y * sc; o.y = vy > 0.f ? vy : 0.01f * vy;
    float vz = acc.z * sc; o.z = vz > 0.f ? vz : 0.01f * vz;
    float vw = acc.w * sc; o.w = vw > 0.f ? vw : 0.01f * vw;
    ((float4*)g_updated)[(size_t)(rbase + row) * 16 + cg] = o;
}

// ---------------------------------------------------------------------------
// CSR build: zero -> histogram -> scan -> fill
// ---------------------------------------------------------------------------
__global__ void k_zero() {
    int t = blockIdx.x * blockDim.x + threadIdx.x;
    if (t < NN) g_cursor[t] = 0;
}

__global__ void k_hist(const int* __restrict__ ei) {
    int t = blockIdx.x * blockDim.x + threadIdx.x;
    if (t < EE) atomicAdd(&g_cursor[ei[EE + t]], 1);   // dst = ei[1][e]
}

__global__ void __launch_bounds__(1024) k_scan() {
    __shared__ int partial[1024];
    int t = threadIdx.x;
    const int CH = (NN + 1023) / 1024;
    int b = t * CH;
    int e = b + CH; if (e > NN) e = NN; if (b > NN) b = NN;
    int s = 0;
    for (int i = b; i < e; ++i) s += g_cursor[i];
    partial[t] = s;
    __syncthreads();
    for (int off = 1; off < 1024; off <<= 1) {
        int v = partial[t];
        int add = (t >= off) ? partial[t - off] : 0;
        __syncthreads();
        partial[t] = v + add;
        __syncthreads();
    }
    int run = (t == 0) ? 0 : partial[t - 1];
    for (int i = b; i < e; ++i) {
        int d = g_cursor[i];
        g_rowptr[i] = run;
        g_cursor[i] = run;
        run += d;
    }
    if (t == 1023) g_rowptr[NN] = partial[1023];
}

__global__ void k_fill(const int* __restrict__ ei) {
    int t = blockIdx.x * blockDim.x + threadIdx.x;
    if (t < EE) {
        int d = ei[EE + t];
        int p = atomicAdd(&g_cursor[d], 1);
        g_col[p] = ei[t];                               // src = ei[0][e]
    }
}

// ---------------------------------------------------------------------------
// Pass A: sum_neigh[i] = sum_j u[j]; fused: sel_v[i] from softmax(relu(.@Wpl))
// One warp per node; lane holds cols [2l, 2l+1] as float2.
// ---------------------------------------------------------------------------
__global__ void __launch_bounds__(256) k_aggA(const float* __restrict__ Wpl) {
    int gw = (blockIdx.x * blockDim.x + threadIdx.x) >> 5;
    int lane = threadIdx.x & 31;
    if (gw >= NN) return;
    int s = g_rowptr[gw], e = g_rowptr[gw + 1];
    const float2* U = (const float2*)g_updated;
    float2 acc = make_float2(0.f, 0.f);
    for (int base = s; base < e; base += 32) {
        int cnt = e - base; if (cnt > 32) cnt = 32;
        int jreg = (lane < cnt) ? g_col[base + lane] : 0;
        for (int q = 0; q < cnt; ++q) {
            int j = __shfl_sync(0xffffffffu, jreg, q);
            float2 u = U[(size_t)j * 32 + lane];
            acc.x += u.x; acc.y += u.y;
        }
    }
    ((float2*)g_sumneigh)[(size_t)gw * 32 + lane] = acc;

    // fused: z = sum_neigh @ W_pl (64x2); sel = softmax(relu(z))[1] > T
    float4 wp = ((const float4*)Wpl)[lane];  // W_pl[2l][0..1], W_pl[2l+1][0..1]
    float a0 = acc.x * wp.x + acc.y * wp.z;
    float a1 = acc.x * wp.y + acc.y * wp.w;
    #pragma unroll
    for (int o = 16; o; o >>= 1) {
        a0 += __shfl_xor_sync(0xffffffffu, a0, o);
        a1 += __shfl_xor_sync(0xffffffffu, a1, o);
    }
    if (lane == 0) {
        float r0 = fmaxf(a0, 0.f), r1 = fmaxf(a1, 0.f);
        float p1 = 1.0f / (1.0f + expf(r0 - r1));
        g_sel[gw] = (p1 > THRESH) ? 1.0f : 0.0f;
    }
}

// ---------------------------------------------------------------------------
// Pass B: sum_sel[i] = sum_j sel[j]*u[j] (regs only); fused:
//   gate[i] = sigmoid(concat([sum_sel, sum_neigh]) @ W_lw) * sel[i]
// ---------------------------------------------------------------------------
__global__ void __launch_bounds__(256) k_aggB(const float* __restrict__ Wlw) {
    int gw = (blockIdx.x * blockDim.x + threadIdx.x) >> 5;
    int lane = threadIdx.x & 31;
    if (gw >= NN) return;
    int s = g_rowptr[gw], e = g_rowptr[gw + 1];
    const float2* U = (const float2*)g_updated;
    float2 acc = make_float2(0.f, 0.f);
    for (int base = s; base < e; base += 32) {
        int cnt = e - base; if (cnt > 32) cnt = 32;
        int jreg = (lane < cnt) ? g_col[base + lane] : 0;
        for (int q = 0; q < cnt; ++q) {
            int j = __shfl_sync(0xffffffffu, jreg, q);
            if (g_sel[j] != 0.f) {                    // warp-uniform skip
                float2 u = U[(size_t)j * 32 + lane];
                acc.x += u.x; acc.y += u.y;
            }
        }
    }
    float2 sn = ((const float2*)g_sumneigh)[(size_t)gw * 32 + lane];
    float2 wl0 = ((const float2*)Wlw)[lane];        // W_lw[2l], W_lw[2l+1]
    float2 wl1 = ((const float2*)Wlw)[32 + lane];   // W_lw[64+2l], [64+2l+1]
    float z = acc.x * wl0.x + acc.y * wl0.y + sn.x * wl1.x + sn.y * wl1.y;
    #pragma unroll
    for (int o = 16; o; o >>= 1) z += __shfl_xor_sync(0xffffffffu, z, o);
    if (lane == 0) {
        float ws = 1.0f / (1.0f + expf(-z));
        g_gate[gw] = ws * g_sel[gw];
    }
}

// ---------------------------------------------------------------------------
// Pass C: a_x[i] = relu(sum_j gate[j]*u[j]); out = proj(expmap0(u[i]+a_x))
// ---------------------------------------------------------------------------
__global__ void __launch_bounds__(256) k_aggC(float* __restrict__ out) {
    int gw = (blockIdx.x * blockDim.x + threadIdx.x) >> 5;
    int lane = threadIdx.x & 31;
    if (gw >= NN) return;
    int s = g_rowptr[gw], e = g_rowptr[gw + 1];
    const float2* U = (const float2*)g_updated;
    float2 acc = make_float2(0.f, 0.f);
    for (int base = s; base < e; base += 32) {
        int cnt = e - base; if (cnt > 32) cnt = 32;
        int jreg = (lane < cnt) ? g_col[base + lane] : 0;
        for (int q = 0; q < cnt; ++q) {
            int j = __shfl_sync(0xffffffffu, jreg, q);
            float g = g_gate[j];
            if (g != 0.f) {
                float2 u = U[(size_t)j * 32 + lane];
                acc.x = fmaf(g, u.x, acc.x);
                acc.y = fmaf(g, u.y, acc.y);
            }
        }
    }
    float2 ui = U[(size_t)gw * 32 + lane];
    float ox = ui.x + fmaxf(acc.x, 0.f);
    float oy = ui.y + fmaxf(acc.y, 0.f);
    float ss = ox * ox + oy * oy;
    #pragma unroll
    for (int o = 16; o; o >>= 1) ss += __shfl_xor_sync(0xffffffffu, ss, o);
    float n = fmaxf(sqrtf(ss), 1e-15f);
    float th = tanhf(n);
    // expmap0: *th/n ; proj: if ||res||(=th) > MAXN scale by MAXN/th
    float f = (th > MAXN) ? (MAXN / n) : (th / n);
    ((float2*)out)[(size_t)gw * 32 + lane] = make_float2(ox * f, oy * f);
}

// ---------------------------------------------------------------------------
extern "C" void kernel_launch(void* const* d_in, const int* in_sizes, int n_in,
                              void* d_out, int out_size) {
    const float* x   = (const float*)d_in[0];
    const int*   ei  = (const int*)  d_in[1];
    const float* Wup = (const float*)d_in[2];
    const float* Wpl = (const float*)d_in[3];
    const float* Wlw = (const float*)d_in[4];
    float* out = (float*)d_out;

    (void)in_sizes; (void)n_in; (void)out_size;

    // GEMM + logmap (independent of CSR build; issue first)
    k_up<<<NN / 16, 256>>>(x, Wup);

    // CSR build
    k_zero<<<(NN + 255) / 256, 256>>>();
    k_hist<<<(EE + 255) / 256, 256>>>(ei);
    k_scan<<<1, 1024>>>();
    k_fill<<<(EE + 255) / 256, 256>>>(ei);

    // three sequential gated aggregation passes (pull-based, L2-resident)
    int aggBlocks = (NN * 32 + 255) / 256;
    k_aggA<<<aggBlocks, 256>>>(Wpl);
    k_aggB<<<aggBlocks, 256>>>(Wlw);
    k_aggC<<<aggBlocks, 256>>>(out);
}

// round 4
// speedup vs baseline: 1.4672x; 1.4672x over previous
#include <cuda_runtime.h>
#include <math.h>

#define NN   100000
#define EE   1600000
#define FIN  128
#define FOUT 64
#define THRESH 0.48f
#define MAXN   (1.0f - 4e-3f)

#define SCAN_B 1024
#define NBLK   ((NN + SCAN_B - 1) / SCAN_B)   // 98

// -------- scratch (device globals; no allocation allowed) --------
__device__ float g_updated [NN * FOUT];   // leaky_relu(logmap0(x) @ W_up)
__device__ float g_sumneigh[NN * FOUT];   // pass A result
__device__ float g_sel     [NN];          // hard gate per node (0/1)
__device__ float g_gate    [NN];          // weight_sel * sel
__device__ int   g_rowptr  [NN + 1];
__device__ int   g_cursor  [NN];
__device__ int   g_col     [EE];
__device__ int   g_blocksum[NBLK];
__device__ int   g_blockoff[NBLK];

// ---------------------------------------------------------------------------
// K1: logmap0 + GEMM (x_tan @ W_up) + leaky_relu  -> g_updated
// ---------------------------------------------------------------------------
__global__ void __launch_bounds__(256) k_up(const float* __restrict__ x,
                                            const float* __restrict__ Wup) {
    __shared__ float  xs[16][FIN];
    __shared__ float4 Ws[FIN * 16];     // W_up as [k][16 x float4] = [128][64]
    __shared__ float  sscale[16];

    int t = threadIdx.x;
    int rbase = blockIdx.x * 16;

    const float4* W4 = (const float4*)Wup;
    #pragma unroll
    for (int i = t; i < FIN * 16; i += 256) Ws[i] = W4[i];
    #pragma unroll
    for (int i = t; i < 16 * FIN; i += 256)
        xs[i >> 7][i & 127] = x[(size_t)rbase * FIN + i];
    __syncthreads();

    int w = t >> 5, lane = t & 31;
    #pragma unroll
    for (int rr = 0; rr < 2; ++rr) {
        int r = w * 2 + rr;
        float v0 = xs[r][lane], v1 = xs[r][lane + 32];
        float v2 = xs[r][lane + 64], v3 = xs[r][lane + 96];
        float s = v0 * v0 + v1 * v1 + v2 * v2 + v3 * v3;
        #pragma unroll
        for (int o = 16; o; o >>= 1) s += __shfl_xor_sync(0xffffffffu, s, o);
        if (lane == 0) {
            float n = fmaxf(sqrtf(s), 1e-15f);
            float a = fminf(fmaxf(n, -1.0f + 1e-7f), 1.0f - 1e-7f);
            float art = 0.5f * (log1pf(a) - log1pf(-a));
            sscale[r] = art / n;
        }
    }
    __syncthreads();

    int row = t >> 4;        // 0..15
    int cg  = t & 15;        // 16 col groups of 4
    float4 acc = make_float4(0.f, 0.f, 0.f, 0.f);
    #pragma unroll 8
    for (int k = 0; k < FIN; ++k) {
        float xv = xs[row][k];
        float4 wv = Ws[k * 16 + cg];
        acc.x = fmaf(xv, wv.x, acc.x);
        acc.y = fmaf(xv, wv.y, acc.y);
        acc.z = fmaf(xv, wv.z, acc.z);
        acc.w = fmaf(xv, wv.w, acc.w);
    }
    float sc = sscale[row];
    float4 o;
    float vx = acc.x * sc; o.x = vx > 0.f ? vx : 0.01f * vx;
    float vy = acc.y * sc; o.y = vy > 0.f ? vy : 0.01f * vy;
    float vz = acc.z * sc; o.z = vz > 0.f ? vz : 0.01f * vz;
    float vw = acc.w * sc; o.w = vw > 0.f ? vw : 0.01f * vw;
    ((float4*)g_updated)[(size_t)(rbase + row) * 16 + cg] = o;
}

// ---------------------------------------------------------------------------
// CSR build: zero -> histogram -> parallel scan (3 kernels) -> fill
// ---------------------------------------------------------------------------
__global__ void k_zero() {
    int t = blockIdx.x * blockDim.x + threadIdx.x;
    if (t < NN) g_cursor[t] = 0;
}

__global__ void k_hist(const int* __restrict__ ei) {
    int t = blockIdx.x * blockDim.x + threadIdx.x;
    if (t < EE) atomicAdd(&g_cursor[ei[EE + t]], 1);   // dst = ei[1][e]
}

// scan stage 1: per-block inclusive scan; write block-exclusive to rowptr,
// block total to g_blocksum.
__global__ void __launch_bounds__(SCAN_B) k_scan1() {
    __shared__ int wsum[32];
    int t = threadIdx.x, b = blockIdx.x;
    int idx = b * SCAN_B + t;
    int lane = t & 31, w = t >> 5;
    int c = (idx < NN) ? g_cursor[idx] : 0;
    int v = c;
    #pragma unroll
    for (int o = 1; o < 32; o <<= 1) {
        int n = __shfl_up_sync(0xffffffffu, v, o);
        if (lane >= o) v += n;
    }
    if (lane == 31) wsum[w] = v;
    __syncthreads();
    if (w == 0) {
        int s = wsum[lane];
        #pragma unroll
        for (int o = 1; o < 32; o <<= 1) {
            int n = __shfl_up_sync(0xffffffffu, s, o);
            if (lane >= o) s += n;
        }
        wsum[lane] = s;
    }
    __syncthreads();
    int base = (w > 0) ? wsum[w - 1] : 0;
    int incl = v + base;
    if (idx < NN) g_rowptr[idx] = incl - c;       // exclusive within block
    if (t == SCAN_B - 1) g_blocksum[b] = incl;    // block total
}

// scan stage 2: exclusive scan of NBLK (=98) block sums, single block.
__global__ void __launch_bounds__(128) k_scan2() {
    __shared__ int s[128];
    int t = threadIdx.x;
    int v = (t < NBLK) ? g_blocksum[t] : 0;
    s[t] = v;
    __syncthreads();
    #pragma unroll
    for (int o = 1; o < 128; o <<= 1) {
        int a = (t >= o) ? s[t - o] : 0;
        __syncthreads();
        s[t] += a;
        __syncthreads();
    }
    if (t < NBLK) g_blockoff[t] = s[t] - v;       // exclusive
}

// scan stage 3: add block offsets; init cursor; cap rowptr.
__global__ void __launch_bounds__(SCAN_B) k_scan3() {
    int idx = blockIdx.x * SCAN_B + threadIdx.x;
    if (idx < NN) {
        int r = g_rowptr[idx] + g_blockoff[blockIdx.x];
        g_rowptr[idx] = r;
        g_cursor[idx] = r;
    }
    if (idx == 0) g_rowptr[NN] = EE;
}

__global__ void k_fill(const int* __restrict__ ei) {
    int t = blockIdx.x * blockDim.x + threadIdx.x;
    if (t < EE) {
        int d = ei[EE + t];
        int p = atomicAdd(&g_cursor[d], 1);
        g_col[p] = ei[t];                               // src = ei[0][e]
    }
}

// ---------------------------------------------------------------------------
// Pass A: sum_neigh[i] = sum_j u[j]; fused: sel_v[i] from softmax(relu(.@Wpl))
// One warp per node; lane holds cols [2l, 2l+1] as float2.
// ---------------------------------------------------------------------------
__global__ void __launch_bounds__(256) k_aggA(const float* __restrict__ Wpl) {
    int gw = (blockIdx.x * blockDim.x + threadIdx.x) >> 5;
    int lane = threadIdx.x & 31;
    if (gw >= NN) return;
    int s = g_rowptr[gw], e = g_rowptr[gw + 1];
    const float2* U = (const float2*)g_updated;
    float2 acc = make_float2(0.f, 0.f);
    for (int base = s; base < e; base += 32) {
        int cnt = e - base; if (cnt > 32) cnt = 32;
        int jreg = (lane < cnt) ? g_col[base + lane] : 0;
        for (int q = 0; q < cnt; ++q) {
            int j = __shfl_sync(0xffffffffu, jreg, q);
            float2 u = U[(size_t)j * 32 + lane];
            acc.x += u.x; acc.y += u.y;
        }
    }
    ((float2*)g_sumneigh)[(size_t)gw * 32 + lane] = acc;

    // fused: z = sum_neigh @ W_pl (64x2); sel = softmax(relu(z))[1] > T
    float4 wp = ((const float4*)Wpl)[lane];  // W_pl[2l][0..1], W_pl[2l+1][0..1]
    float a0 = acc.x * wp.x + acc.y * wp.z;
    float a1 = acc.x * wp.y + acc.y * wp.w;
    #pragma unroll
    for (int o = 16; o; o >>= 1) {
        a0 += __shfl_xor_sync(0xffffffffu, a0, o);
        a1 += __shfl_xor_sync(0xffffffffu, a1, o);
    }
    if (lane == 0) {
        float r0 = fmaxf(a0, 0.f), r1 = fmaxf(a1, 0.f);
        float p1 = 1.0f / (1.0f + expf(r0 - r1));
        g_sel[gw] = (p1 > THRESH) ? 1.0f : 0.0f;
    }
}

// ---------------------------------------------------------------------------
// Pass B: sum_sel[i] = sum_j sel[j]*u[j] (regs only); fused:
//   gate[i] = sigmoid(concat([sum_sel, sum_neigh]) @ W_lw) * sel[i]
// ---------------------------------------------------------------------------
__global__ void __launch_bounds__(256) k_aggB(const float* __restrict__ Wlw) {
    int gw = (blockIdx.x * blockDim.x + threadIdx.x) >> 5;
    int lane = threadIdx.x & 31;
    if (gw >= NN) return;
    int s = g_rowptr[gw], e = g_rowptr[gw + 1];
    const float2* U = (const float2*)g_updated;
    float2 acc = make_float2(0.f, 0.f);
    for (int base = s; base < e; base += 32) {
        int cnt = e - base; if (cnt > 32) cnt = 32;
        int jreg = (lane < cnt) ? g_col[base + lane] : 0;
        for (int q = 0; q < cnt; ++q) {
            int j = __shfl_sync(0xffffffffu, jreg, q);
            if (g_sel[j] != 0.f) {                    // warp-uniform skip
                float2 u = U[(size_t)j * 32 + lane];
                acc.x += u.x; acc.y += u.y;
            }
        }
    }
    float2 sn = ((const float2*)g_sumneigh)[(size_t)gw * 32 + lane];
    float2 wl0 = ((const float2*)Wlw)[lane];        // W_lw[2l], W_lw[2l+1]
    float2 wl1 = ((const float2*)Wlw)[32 + lane];   // W_lw[64+2l], [64+2l+1]
    float z = acc.x * wl0.x + acc.y * wl0.y + sn.x * wl1.x + sn.y * wl1.y;
    #pragma unroll
    for (int o = 16; o; o >>= 1) z += __shfl_xor_sync(0xffffffffu, z, o);
    if (lane == 0) {
        float ws = 1.0f / (1.0f + expf(-z));
        g_gate[gw] = ws * g_sel[gw];
    }
}

// ---------------------------------------------------------------------------
// Pass C: a_x[i] = relu(sum_j gate[j]*u[j]); out = proj(expmap0(u[i]+a_x))
// ---------------------------------------------------------------------------
__global__ void __launch_bounds__(256) k_aggC(float* __restrict__ out) {
    int gw = (blockIdx.x * blockDim.x + threadIdx.x) >> 5;
    int lane = threadIdx.x & 31;
    if (gw >= NN) return;
    int s = g_rowptr[gw], e = g_rowptr[gw + 1];
    const float2* U = (const float2*)g_updated;
    float2 acc = make_float2(0.f, 0.f);
    for (int base = s; base < e; base += 32) {
        int cnt = e - base; if (cnt > 32) cnt = 32;
        int jreg = (lane < cnt) ? g_col[base + lane] : 0;
        for (int q = 0; q < cnt; ++q) {
            int j = __shfl_sync(0xffffffffu, jreg, q);
            float g = g_gate[j];
            if (g != 0.f) {
                float2 u = U[(size_t)j * 32 + lane];
                acc.x = fmaf(g, u.x, acc.x);
                acc.y = fmaf(g, u.y, acc.y);
            }
        }
    }
    float2 ui = U[(size_t)gw * 32 + lane];
    float ox = ui.x + fmaxf(acc.x, 0.f);
    float oy = ui.y + fmaxf(acc.y, 0.f);
    float ss = ox * ox + oy * oy;
    #pragma unroll
    for (int o = 16; o; o >>= 1) ss += __shfl_xor_sync(0xffffffffu, ss, o);
    float n = fmaxf(sqrtf(ss), 1e-15f);
    float th = tanhf(n);
    float f = (th > MAXN) ? (MAXN / n) : (th / n);
    ((float2*)out)[(size_t)gw * 32 + lane] = make_float2(ox * f, oy * f);
}

// ---------------------------------------------------------------------------
extern "C" void kernel_launch(void* const* d_in, const int* in_sizes, int n_in,
                              void* d_out, int out_size) {
    const float* x   = (const float*)d_in[0];
    const int*   ei  = (const int*)  d_in[1];
    const float* Wup = (const float*)d_in[2];
    const float* Wpl = (const float*)d_in[3];
    const float* Wlw = (const float*)d_in[4];
    float* out = (float*)d_out;

    (void)in_sizes; (void)n_in; (void)out_size;

    // GEMM + logmap (independent of CSR build; issue first)
    k_up<<<NN / 16, 256>>>(x, Wup);

    // CSR build
    k_zero<<<(NN + 255) / 256, 256>>>();
    k_hist<<<(EE + 255) / 256, 256>>>(ei);
    k_scan1<<<NBLK, SCAN_B>>>();
    k_scan2<<<1, 128>>>();
    k_scan3<<<NBLK, SCAN_B>>>();
    k_fill<<<(EE + 255) / 256, 256>>>(ei);

    // three sequential gated aggregation passes (pull-based, L2-resident)
    int aggBlocks = (NN * 32 + 255) / 256;
    k_aggA<<<aggBlocks, 256>>>(Wpl);
    k_aggB<<<aggBlocks, 256>>>(Wlw);
    k_aggC<<<aggBlocks, 256>>>(out);
}

// round 5
// speedup vs baseline: 1.8265x; 1.2449x over previous
#include <cuda_runtime.h>
#include <math.h>

#define NN   100000
#define EE   1600000
#define FIN  128
#define FOUT 64
#define THRESH 0.48f
#define MAXN   (1.0f - 4e-3f)

#define SCAN_B 1024
#define NBLK   ((NN + SCAN_B - 1) / SCAN_B)   // 98

#define GEMM_ROWS   32
#define GEMM_BLOCKS (NN / GEMM_ROWS)          // 3125
#define ZERO_BLOCKS ((NN + 255) / 256)        // 391

typedef unsigned long long u64;

// -------- scratch (device globals; no allocation allowed) --------
__device__ float g_updated [NN * FOUT];
__device__ float g_sumneigh[NN * FOUT];
__device__ float g_sel     [NN];
__device__ float g_gate    [NN];
__device__ int   g_rowptr  [NN + 1];
__device__ int   g_cursor  [NN];
__device__ int   g_col     [EE];
__device__ int   g_blocksum[NBLK];
__device__ int   g_blockoff[NBLK];

// ---- f32x2 helpers ----
__device__ __forceinline__ u64 pack2(float lo, float hi) {
    u64 r; asm("mov.b64 %0,{%1,%2};" : "=l"(r) : "f"(lo), "f"(hi)); return r;
}
__device__ __forceinline__ void unpack2(u64 v, float& lo, float& hi) {
    asm("mov.b64 {%0,%1},%2;" : "=f"(lo), "=f"(hi) : "l"(v));
}
__device__ __forceinline__ u64 add2(u64 a, u64 b) {
    u64 d; asm("add.rn.f32x2 %0,%1,%2;" : "=l"(d) : "l"(a), "l"(b)); return d;
}
__device__ __forceinline__ u64 fma2(u64 a, u64 b, u64 c) {
    u64 d; asm("fma.rn.f32x2 %0,%1,%2,%3;" : "=l"(d) : "l"(a), "l"(b), "l"(c)); return d;
}

// ---------------------------------------------------------------------------
// K1: logmap0 + GEMM (x_tan @ W_up) + leaky_relu -> g_updated. 32 rows/block,
// f32x2 FMAs (column pairs), each thread covers 2 rows (W-load reuse).
// Extra trailing blocks zero g_cursor (folds k_zero launch in).
// ---------------------------------------------------------------------------
__global__ void __launch_bounds__(256) k_up(const float* __restrict__ x,
                                            const float* __restrict__ Wup) {
    if (blockIdx.x >= GEMM_BLOCKS) {
        int i = (blockIdx.x - GEMM_BLOCKS) * 256 + threadIdx.x;
        if (i < NN) g_cursor[i] = 0;
        return;
    }
    __shared__ float  xs[GEMM_ROWS][FIN];
    __shared__ float4 Ws[FIN * 16];          // [k][16 col-groups of 4]
    __shared__ float  sscale[GEMM_ROWS];

    int t = threadIdx.x;
    int rbase = blockIdx.x * GEMM_ROWS;

    const float4* W4 = (const float4*)Wup;
    #pragma unroll
    for (int i = t; i < FIN * 16; i += 256) Ws[i] = W4[i];
    #pragma unroll
    for (int i = t; i < GEMM_ROWS * FIN; i += 256)
        xs[i >> 7][i & 127] = x[(size_t)rbase * FIN + i];
    __syncthreads();

    int w = t >> 5, lane = t & 31;
    #pragma unroll
    for (int rr = 0; rr < 4; ++rr) {
        int r = w * 4 + rr;
        float v0 = xs[r][lane], v1 = xs[r][lane + 32];
        float v2 = xs[r][lane + 64], v3 = xs[r][lane + 96];
        float s = v0 * v0 + v1 * v1 + v2 * v2 + v3 * v3;
        #pragma unroll
        for (int o = 16; o; o >>= 1) s += __shfl_xor_sync(0xffffffffu, s, o);
        if (lane == 0) {
            float n = fmaxf(sqrtf(s), 1e-15f);
            float a = fminf(fmaxf(n, -1.0f + 1e-7f), 1.0f - 1e-7f);
            float art = 0.5f * (log1pf(a) - log1pf(-a));
            sscale[r] = art / n;
        }
    }
    __syncthreads();

    int rp = t >> 4;          // 0..15 -> rows rp, rp+16
    int cg = t & 15;          // col group of 4
    int r0 = rp, r1 = rp + 16;
    u64 a00 = 0, a01 = 0, a10 = 0, a11 = 0;   // {c0,c1},{c2,c3} x 2 rows

    #pragma unroll 4
    for (int k = 0; k < FIN; ++k) {
        float4 wv = Ws[k * 16 + cg];
        u64 w01 = pack2(wv.x, wv.y);
        u64 w23 = pack2(wv.z, wv.w);
        float xv0 = xs[r0][k], xv1 = xs[r1][k];
        u64 xa = pack2(xv0, xv0);
        u64 xb = pack2(xv1, xv1);
        a00 = fma2(xa, w01, a00);
        a01 = fma2(xa, w23, a01);
        a10 = fma2(xb, w01, a10);
        a11 = fma2(xb, w23, a11);
    }

    #pragma unroll
    for (int rr = 0; rr < 2; ++rr) {
        int r = rr ? r1 : r0;
        float sc = sscale[r];
        float c0, c1, c2, c3;
        unpack2(rr ? a10 : a00, c0, c1);
        unpack2(rr ? a11 : a01, c2, c3);
        float4 o;
        float v;
        v = c0 * sc; o.x = v > 0.f ? v : 0.01f * v;
        v = c1 * sc; o.y = v > 0.f ? v : 0.01f * v;
        v = c2 * sc; o.z = v > 0.f ? v : 0.01f * v;
        v = c3 * sc; o.w = v > 0.f ? v : 0.01f * v;
        ((float4*)g_updated)[(size_t)(rbase + r) * 16 + cg] = o;
    }
}

// ---------------------------------------------------------------------------
// CSR build
// ---------------------------------------------------------------------------
__global__ void k_hist(const int* __restrict__ ei) {
    int t = blockIdx.x * blockDim.x + threadIdx.x;
    if (t < EE) atomicAdd(&g_cursor[ei[EE + t]], 1);
}

__global__ void __launch_bounds__(SCAN_B) k_scan1() {
    __shared__ int wsum[32];
    int t = threadIdx.x, b = blockIdx.x;
    int idx = b * SCAN_B + t;
    int lane = t & 31, w = t >> 5;
    int c = (idx < NN) ? g_cursor[idx] : 0;
    int v = c;
    #pragma unroll
    for (int o = 1; o < 32; o <<= 1) {
        int n = __shfl_up_sync(0xffffffffu, v, o);
        if (lane >= o) v += n;
    }
    if (lane == 31) wsum[w] = v;
    __syncthreads();
    if (w == 0) {
        int s = wsum[lane];
        #pragma unroll
        for (int o = 1; o < 32; o <<= 1) {
            int n = __shfl_up_sync(0xffffffffu, s, o);
            if (lane >= o) s += n;
        }
        wsum[lane] = s;
    }
    __syncthreads();
    int base = (w > 0) ? wsum[w - 1] : 0;
    int incl = v + base;
    if (idx < NN) g_rowptr[idx] = incl - c;
    if (t == SCAN_B - 1) g_blocksum[b] = incl;
}

__global__ void __launch_bounds__(128) k_scan2() {
    __shared__ int s[128];
    int t = threadIdx.x;
    int v = (t < NBLK) ? g_blocksum[t] : 0;
    s[t] = v;
    __syncthreads();
    #pragma unroll
    for (int o = 1; o < 128; o <<= 1) {
        int a = (t >= o) ? s[t - o] : 0;
        __syncthreads();
        s[t] += a;
        __syncthreads();
    }
    if (t < NBLK) g_blockoff[t] = s[t] - v;
}

__global__ void __launch_bounds__(SCAN_B) k_scan3() {
    int idx = blockIdx.x * SCAN_B + threadIdx.x;
    if (idx < NN) {
        int r = g_rowptr[idx] + g_blockoff[blockIdx.x];
        g_rowptr[idx] = r;
        g_cursor[idx] = r;
    }
    if (idx == 0) g_rowptr[NN] = EE;
}

__global__ void k_fill(const int* __restrict__ ei) {
    int t = blockIdx.x * blockDim.x + threadIdx.x;
    if (t < EE) {
        int d = ei[EE + t];
        int p = atomicAdd(&g_cursor[d], 1);
        g_col[p] = ei[t];
    }
}

// ---------------------------------------------------------------------------
// Pass A: sum_neigh + fused sel gate. Uniform-index gather, 4-way unroll,
// two independent f32x2 accumulators.
// ---------------------------------------------------------------------------
__global__ void __launch_bounds__(256) k_aggA(const float* __restrict__ Wpl) {
    int gw = (blockIdx.x * blockDim.x + threadIdx.x) >> 5;
    int lane = threadIdx.x & 31;
    if (gw >= NN) return;
    int s = g_rowptr[gw], e = g_rowptr[gw + 1];
    const u64* U = (const u64*)g_updated;
    u64 acc0 = 0, acc1 = 0;
    int p = s;
    for (; p + 4 <= e; p += 4) {
        int j0 = __ldg(&g_col[p]);
        int j1 = __ldg(&g_col[p + 1]);
        int j2 = __ldg(&g_col[p + 2]);
        int j3 = __ldg(&g_col[p + 3]);
        u64 u0 = __ldg(&U[(size_t)j0 * 32 + lane]);
        u64 u1 = __ldg(&U[(size_t)j1 * 32 + lane]);
        u64 u2 = __ldg(&U[(size_t)j2 * 32 + lane]);
        u64 u3 = __ldg(&U[(size_t)j3 * 32 + lane]);
        acc0 = add2(acc0, u0);
        acc1 = add2(acc1, u1);
        acc0 = add2(acc0, u2);
        acc1 = add2(acc1, u3);
    }
    for (; p < e; ++p) {
        int j = __ldg(&g_col[p]);
        acc0 = add2(acc0, __ldg(&U[(size_t)j * 32 + lane]));
    }
    u64 accp = add2(acc0, acc1);
    float ax, ay; unpack2(accp, ax, ay);
    ((float2*)g_sumneigh)[(size_t)gw * 32 + lane] = make_float2(ax, ay);

    float4 wp = ((const float4*)Wpl)[lane];
    float a0 = ax * wp.x + ay * wp.z;
    float a1 = ax * wp.y + ay * wp.w;
    #pragma unroll
    for (int o = 16; o; o >>= 1) {
        a0 += __shfl_xor_sync(0xffffffffu, a0, o);
        a1 += __shfl_xor_sync(0xffffffffu, a1, o);
    }
    if (lane == 0) {
        float r0 = fmaxf(a0, 0.f), r1 = fmaxf(a1, 0.f);
        float p1 = 1.0f / (1.0f + expf(r0 - r1));
        g_sel[gw] = (p1 > THRESH) ? 1.0f : 0.0f;
    }
}

// ---------------------------------------------------------------------------
// Pass B: sum over selected neighbors -> gate
// ---------------------------------------------------------------------------
__global__ void __launch_bounds__(256) k_aggB(const float* __restrict__ Wlw) {
    int gw = (blockIdx.x * blockDim.x + threadIdx.x) >> 5;
    int lane = threadIdx.x & 31;
    if (gw >= NN) return;
    int s = g_rowptr[gw], e = g_rowptr[gw + 1];
    const u64* U = (const u64*)g_updated;
    u64 acc0 = 0, acc1 = 0;
    int p = s;
    for (; p + 4 <= e; p += 4) {
        int j0 = __ldg(&g_col[p]);
        int j1 = __ldg(&g_col[p + 1]);
        int j2 = __ldg(&g_col[p + 2]);
        int j3 = __ldg(&g_col[p + 3]);
        float s0 = __ldg(&g_sel[j0]), s1 = __ldg(&g_sel[j1]);
        float s2 = __ldg(&g_sel[j2]), s3 = __ldg(&g_sel[j3]);
        if (s0 != 0.f) acc0 = add2(acc0, __ldg(&U[(size_t)j0 * 32 + lane]));
        if (s1 != 0.f) acc1 = add2(acc1, __ldg(&U[(size_t)j1 * 32 + lane]));
        if (s2 != 0.f) acc0 = add2(acc0, __ldg(&U[(size_t)j2 * 32 + lane]));
        if (s3 != 0.f) acc1 = add2(acc1, __ldg(&U[(size_t)j3 * 32 + lane]));
    }
    for (; p < e; ++p) {
        int j = __ldg(&g_col[p]);
        if (__ldg(&g_sel[j]) != 0.f)
            acc0 = add2(acc0, __ldg(&U[(size_t)j * 32 + lane]));
    }
    u64 accp = add2(acc0, acc1);
    float ax, ay; unpack2(accp, ax, ay);
    float2 sn = ((const float2*)g_sumneigh)[(size_t)gw * 32 + lane];
    float2 wl0 = ((const float2*)Wlw)[lane];
    float2 wl1 = ((const float2*)Wlw)[32 + lane];
    float z = ax * wl0.x + ay * wl0.y + sn.x * wl1.x + sn.y * wl1.y;
    #pragma unroll
    for (int o = 16; o; o >>= 1) z += __shfl_xor_sync(0xffffffffu, z, o);
    if (lane == 0) {
        float ws = 1.0f / (1.0f + expf(-z));
        g_gate[gw] = ws * g_sel[gw];
    }
}

// ---------------------------------------------------------------------------
// Pass C: a_x = relu(sum gate[j]*u[j]); out = proj(expmap0(u + a_x))
// ---------------------------------------------------------------------------
__global__ void __launch_bounds__(256) k_aggC(float* __restrict__ out) {
    int gw = (blockIdx.x * blockDim.x + threadIdx.x) >> 5;
    int lane = threadIdx.x & 31;
    if (gw >= NN) return;
    int s = g_rowptr[gw], e = g_rowptr[gw + 1];
    const u64* U = (const u64*)g_updated;
    u64 acc0 = 0, acc1 = 0;
    int p = s;
    for (; p + 4 <= e; p += 4) {
        int j0 = __ldg(&g_col[p]);
        int j1 = __ldg(&g_col[p + 1]);
        int j2 = __ldg(&g_col[p + 2]);
        int j3 = __ldg(&g_col[p + 3]);
        float g0 = __ldg(&g_gate[j0]), g1 = __ldg(&g_gate[j1]);
        float g2 = __ldg(&g_gate[j2]), g3 = __ldg(&g_gate[j3]);
        if (g0 != 0.f) acc0 = fma2(pack2(g0, g0), __ldg(&U[(size_t)j0 * 32 + lane]), acc0);
        if (g1 != 0.f) acc1 = fma2(pack2(g1, g1), __ldg(&U[(size_t)j1 * 32 + lane]), acc1);
        if (g2 != 0.f) acc0 = fma2(pack2(g2, g2), __ldg(&U[(size_t)j2 * 32 + lane]), acc0);
        if (g3 != 0.f) acc1 = fma2(pack2(g3, g3), __ldg(&U[(size_t)j3 * 32 + lane]), acc1);
    }
    for (; p < e; ++p) {
        int j = __ldg(&g_col[p]);
        float g = __ldg(&g_gate[j]);
        if (g != 0.f)
            acc0 = fma2(pack2(g, g), __ldg(&U[(size_t)j * 32 + lane]), acc0);
    }
    u64 accp = add2(acc0, acc1);
    float ax, ay; unpack2(accp, ax, ay);
    float2 ui = ((const float2*)g_updated)[(size_t)gw * 32 + lane];
    float ox = ui.x + fmaxf(ax, 0.f);
    float oy = ui.y + fmaxf(ay, 0.f);
    float ss = ox * ox + oy * oy;
    #pragma unroll
    for (int o = 16; o; o >>= 1) ss += __shfl_xor_sync(0xffffffffu, ss, o);
    float n = fmaxf(sqrtf(ss), 1e-15f);
    float th = tanhf(n);
    float f = (th > MAXN) ? (MAXN / n) : (th / n);
    ((float2*)out)[(size_t)gw * 32 + lane] = make_float2(ox * f, oy * f);
}

// ---------------------------------------------------------------------------
extern "C" void kernel_launch(void* const* d_in, const int* in_sizes, int n_in,
                              void* d_out, int out_size) {
    const float* x   = (const float*)d_in[0];
    const int*   ei  = (const int*)  d_in[1];
    const float* Wup = (const float*)d_in[2];
    const float* Wpl = (const float*)d_in[3];
    const float* Wlw = (const float*)d_in[4];
    float* out = (float*)d_out;

    (void)in_sizes; (void)n_in; (void)out_size;

    // GEMM + logmap; trailing blocks zero g_cursor for the CSR build
    k_up<<<GEMM_BLOCKS + ZERO_BLOCKS, 256>>>(x, Wup);

    k_hist<<<(EE + 255) / 256, 256>>>(ei);
    k_scan1<<<NBLK, SCAN_B>>>();
    k_scan2<<<1, 128>>>();
    k_scan3<<<NBLK, SCAN_B>>>();
    k_fill<<<(EE + 255) / 256, 256>>>(ei);

    int aggBlocks = (NN * 32 + 255) / 256;
    k_aggA<<<aggBlocks, 256>>>(Wpl);
    k_aggB<<<aggBlocks, 256>>>(Wlw);
    k_aggC<<<aggBlocks, 256>>>(out);
}